// round 11
// baseline (speedup 1.0000x reference)
#include <cuda_runtime.h>
#include <cuda_fp16.h>
#include <math.h>
#include <stdint.h>

#define BATCH   4
#define SEQ     4096
#define HID     2048
#define HEADD   256
#define VDIM    512
#define MROWS   (BATCH*SEQ)

#define LOG2_GAMMA (-0.045803686185410744f)
#define GAMMA_INV  (1.0322580645161290f)
#define GAMMA_P8   (0.7756998776f)
#define GAMMA_M8   (1.2891590567f)
#define WINDOW     10

// proj tile geometry
#define PA 40                      // A pitch (halfs)
#define PB 264                     // B pitch (halfs), N=256 + 8 pad
#define A_ST (128 * PA)            // 5120 halfs / stage
#define B_ST (32 * PB)             // 8448 halfs / stage
#define A_BYTES (A_ST * 2)         // 10240
#define B_BYTES (B_ST * 2)         // 16896

// Scratch (__device__ globals: allocation-free rule)
__device__ __half g_Xp[(size_t)128 * 64 * A_ST];   // X packed [mtile][stage][row][PA], 84 MB
__device__ __half g_Wp[(size_t)4 * 64 * B_ST];     // W*1024 packed [job][stage][krow][PB], 4.3 MB
__device__ float  g_Q [(size_t)MROWS * HEADD];     // Qrot * sv^{+q/512}
__device__ float  g_K [(size_t)MROWS * HEADD];     // Krot * sv^{-k/512}
__device__ __half g_Vh[(size_t)MROWS * VDIM];      // V*64 fp16

// ---------------------------------------------------------------------------
__device__ __forceinline__ uint32_t smem_u32(const void* p) {
    uint32_t a;
    asm("{ .reg .u64 t; cvta.to.shared.u64 t, %1; cvt.u32.u64 %0, t; }" : "=r"(a) : "l"(p));
    return a;
}
__device__ __forceinline__ void cp_async16(uint32_t s, const void* g) {
    asm volatile("cp.async.cg.shared.global [%0], [%1], 16;" :: "r"(s), "l"(g) : "memory");
}
#define CP_COMMIT()  asm volatile("cp.async.commit_group;" ::: "memory")
#define CP_WAIT(N)   asm volatile("cp.async.wait_group %0;" :: "n"(N) : "memory")

#define MBAR_INIT(a, cnt) asm volatile("mbarrier.init.shared.b64 [%0], %1;" :: "r"(a), "r"((uint32_t)(cnt)) : "memory")
#define MBAR_EXPECT_TX(a, bytes) asm volatile("mbarrier.arrive.expect_tx.shared.b64 _, [%0], %1;" :: "r"(a), "r"((uint32_t)(bytes)) : "memory")
#define FENCE_ASYNC() asm volatile("fence.proxy.async.shared::cta;" ::: "memory")

#define MBAR_WAIT(addr, ph) do {                                              \
    uint32_t _m = (addr); uint32_t _p = (ph); uint32_t _d;                    \
    asm volatile("{\n\t.reg .pred p;\n\t"                                     \
        "mbarrier.try_wait.parity.acquire.cta.shared::cta.b64 p, [%1], %2;\n\t" \
        "selp.b32 %0, 1, 0, p;\n\t}" : "=r"(_d) : "r"(_m), "r"(_p) : "memory"); \
    if (!_d) {                                                                \
        asm volatile("{\n\t.reg .pred P1;\n\t"                                \
        "W_%=:\n\tmbarrier.try_wait.parity.acquire.cta.shared::cta.b64 P1, [%0], %1, 0x989680;\n\t" \
        "@P1 bra.uni D_%=;\n\tbra.uni W_%=;\n\tD_%=:\n\t}"                    \
        :: "r"(_m), "r"(_p) : "memory");                                      \
    }                                                                         \
} while (0)

__device__ __forceinline__ void bulk_ld(uint32_t dst, const void* src, uint32_t bytes, uint32_t mbar) {
    asm volatile("cp.async.bulk.shared::cta.global.mbarrier::complete_tx::bytes [%0], [%1], %2, [%3];"
                 :: "r"(dst), "l"(src), "r"(bytes), "r"(mbar) : "memory");
}

__device__ __forceinline__ void ldm_x4(uint32_t* r, uint32_t a) {
    asm volatile("ldmatrix.sync.aligned.m8n8.x4.shared.b16 {%0,%1,%2,%3}, [%4];"
                 : "=r"(r[0]), "=r"(r[1]), "=r"(r[2]), "=r"(r[3]) : "r"(a));
}
__device__ __forceinline__ void ldm_x4t(uint32_t* r, uint32_t a) {
    asm volatile("ldmatrix.sync.aligned.m8n8.x4.trans.shared.b16 {%0,%1,%2,%3}, [%4];"
                 : "=r"(r[0]), "=r"(r[1]), "=r"(r[2]), "=r"(r[3]) : "r"(a));
}
__device__ __forceinline__ void ldm_x2(uint32_t* r, uint32_t a) {
    asm volatile("ldmatrix.sync.aligned.m8n8.x2.shared.b16 {%0,%1}, [%2];"
                 : "=r"(r[0]), "=r"(r[1]) : "r"(a));
}
__device__ __forceinline__ void ldm_x2t(uint32_t* r, uint32_t a) {
    asm volatile("ldmatrix.sync.aligned.m8n8.x2.trans.shared.b16 {%0,%1}, [%2];"
                 : "=r"(r[0]), "=r"(r[1]) : "r"(a));
}
__device__ __forceinline__ void mma16(float* d, const uint32_t* a, const uint32_t* b) {
    asm volatile("mma.sync.aligned.m16n8k16.row.col.f32.f16.f16.f32 "
                 "{%0,%1,%2,%3},{%4,%5,%6,%7},{%8,%9},{%0,%1,%2,%3};"
                 : "+f"(d[0]), "+f"(d[1]), "+f"(d[2]), "+f"(d[3])
                 : "r"(a[0]), "r"(a[1]), "r"(a[2]), "r"(a[3]), "r"(b[0]), "r"(b[1]));
}
__device__ __forceinline__ void mma3(float* d, const uint32_t* ah, const uint32_t* al,
                                     const uint32_t* bh, const uint32_t* bl) {
    mma16(d, ah, bh);
    mma16(d, ah, bl);
    mma16(d, al, bh);
}
__device__ __forceinline__ void hsplit(float x, __half& hi, __half& lo) {
    hi = __float2half_rn(x);
    lo = __float2half_rn(x - __half2float(hi));
}

// ===========================================================================
// Pack kernels: write fp16 operands in the exact padded SMEM-tile layout.
// ===========================================================================
__global__ void __launch_bounds__(256) pack_x_kernel(const float* __restrict__ X)
{
    const int idx = blockIdx.x * 256 + threadIdx.x;   // 4,194,304 total
    const int m  = idx >> 8;
    const int kc = (idx & 255) << 3;
    const float* src = X + (size_t)m * HID + kc;
    float4 a = *(const float4*)(src);
    float4 b = *(const float4*)(src + 4);
    __half2 ph[4];
    ph[0] = __halves2half2(__float2half_rn(a.x), __float2half_rn(a.y));
    ph[1] = __halves2half2(__float2half_rn(a.z), __float2half_rn(a.w));
    ph[2] = __halves2half2(__float2half_rn(b.x), __float2half_rn(b.y));
    ph[3] = __halves2half2(__float2half_rn(b.z), __float2half_rn(b.w));
    __half* dst = g_Xp + ((size_t)(m >> 7) * 64 + (kc >> 5)) * A_ST + (m & 127) * PA + (kc & 31);
    *(uint4*)dst = *(uint4*)ph;
}

__global__ void __launch_bounds__(256) pack_w_kernel(const float* __restrict__ WQ,
                                                     const float* __restrict__ WK,
                                                     const float* __restrict__ WV)
{
    const int idx = blockIdx.x * 256 + threadIdx.x;   // 262,144 total
    const int k  = idx >> 7;
    const int n8 = (idx & 127) << 3;
    const float* src;
    if (n8 < 256)      src = WQ + (size_t)k * 256 + n8;
    else if (n8 < 512) src = WK + (size_t)k * 256 + (n8 - 256);
    else               src = WV + (size_t)k * 512 + (n8 - 512);
    float4 a = *(const float4*)(src);
    float4 b = *(const float4*)(src + 4);
    __half2 ph[4];
    ph[0] = __halves2half2(__float2half_rn(a.x * 1024.0f), __float2half_rn(a.y * 1024.0f));
    ph[1] = __halves2half2(__float2half_rn(a.z * 1024.0f), __float2half_rn(a.w * 1024.0f));
    ph[2] = __halves2half2(__float2half_rn(b.x * 1024.0f), __float2half_rn(b.y * 1024.0f));
    ph[3] = __halves2half2(__float2half_rn(b.z * 1024.0f), __float2half_rn(b.w * 1024.0f));
    __half* dst = g_Wp + ((size_t)(n8 >> 8) * 64 + (k >> 5)) * B_ST + (k & 31) * PB + (n8 & 255);
    *(uint4*)dst = *(uint4*)ph;
}

// ===========================================================================
// Projection: CTA 128x256, BK=32, 3-stage ring fed by 2 cp.async.bulk/stage.
// jobs: 0=Q, 1=K, 2,3=V halves. 8 warps (2x4), warp tile 64x64.
// ===========================================================================
#define APL(s)   ((s) * A_ST)
#define BPL(s)   (3 * A_ST + (s) * B_ST)
#define BAR_OFF  ((3 * A_ST + 3 * B_ST) * 2)
#define PROJ_SMEM (BAR_OFF + 64)

__global__ void __launch_bounds__(256, 1) proj_kernel()
{
    extern __shared__ __align__(16) __half sm[];
    const uint32_t sb = smem_u32(sm);

    const int tid = threadIdx.x, wid = tid >> 5, lane = tid & 31;
    const int g = lane >> 2, tg = lane & 3;
    const int mtile = blockIdx.y;
    const int m0 = mtile * 128;
    const int job = blockIdx.x;

    const int wm = (wid >> 2) * 64, wn = (wid & 3) * 64;
    const int arow_f = lane & 15;
    const int acol_f = (lane >> 4) << 3;
    const int b4row_f = lane & 15;
    const int b4col_f = (lane >> 4) << 3;

    if (tid == 0) {
#pragma unroll
        for (int s = 0; s < 3; s++) MBAR_INIT(sb + BAR_OFF + s * 8, 1);
        FENCE_ASYNC();
    }
    __syncthreads();

    auto issue = [&](int s, int chunk) {
        const uint32_t bar = sb + BAR_OFF + s * 8;
        MBAR_EXPECT_TX(bar, A_BYTES + B_BYTES);
        bulk_ld(sb + (uint32_t)APL(s) * 2,
                g_Xp + ((size_t)mtile * 64 + chunk) * A_ST, A_BYTES, bar);
        bulk_ld(sb + (uint32_t)BPL(s) * 2,
                g_Wp + ((size_t)job * 64 + chunk) * B_ST, B_BYTES, bar);
    };

    if (tid == 0) { issue(0, 0); issue(1, 1); }

    float acc[4][8][4];
#pragma unroll
    for (int a = 0; a < 4; a++)
#pragma unroll
        for (int b = 0; b < 8; b++)
#pragma unroll
            for (int c = 0; c < 4; c++) acc[a][b][c] = 0.0f;

    for (int kb = 0; kb < 64; kb++) {
        const int s = kb % 3;
        MBAR_WAIT(sb + BAR_OFF + s * 8, (kb / 3) & 1);
        __syncthreads();
        if (tid == 0 && kb + 2 < 64) issue((kb + 2) % 3, kb + 2);

#pragma unroll
        for (int k2 = 0; k2 < 2; k2++) {
            const int kk = k2 * 16;
            uint32_t ah[4][4], bh[8][2];
#pragma unroll
            for (int mf = 0; mf < 4; mf++) {
                const uint32_t off = (uint32_t)((wm + mf * 16 + arow_f) * PA + kk + acol_f) * 2;
                ldm_x4(ah[mf], sb + (uint32_t)APL(s) * 2 + off);
            }
#pragma unroll
            for (int p = 0; p < 4; p++) {
                const uint32_t off = (uint32_t)((kk + b4row_f) * PB + wn + p * 16 + b4col_f) * 2;
                ldm_x4t(&bh[p * 2][0], sb + (uint32_t)BPL(s) * 2 + off);
            }
#pragma unroll
            for (int mf = 0; mf < 4; mf++)
#pragma unroll
                for (int nf = 0; nf < 8; nf++)
                    mma16(acc[mf][nf], ah[mf], bh[nf]);
        }
    }

    // ---- epilogue ----
    const int mode = (job == 0) ? 1 : (job == 1) ? 2 : 0;
#pragma unroll
    for (int mf = 0; mf < 4; mf++) {
#pragma unroll
        for (int half = 0; half < 2; half++) {
            const int m = m0 + wm + mf * 16 + g + half * 8;
            const float spos = (float)(m & (SEQ - 1));
#pragma unroll
            for (int nf = 0; nf < 8; nf++) {
                const int ncol = wn + nf * 8 + 2 * tg;
                float e = acc[mf][nf][half * 2]     * (1.0f / 1024.0f);
                float o = acc[mf][nf][half * 2 + 1] * (1.0f / 1024.0f);
                if (mode != 0) {
                    const int nn = ncol;                // head col 0..255
                    const float jj = (float)(nn >> 1);
                    const float invf = powf(10000.0f, -jj * (1.0f / 128.0f));
                    float sn, cs;
                    sincosf(spos * invf, &sn, &cs);
                    float ne = e * cs - o * sn;
                    float no = o * cs + e * sn;
                    const float sv = ((float)nn + 102.4f) * (1.0f / 358.4f);
                    const float sc = powf(sv, (mode == 1 ? spos : -spos) * (1.0f / 512.0f));
                    ne *= sc; no *= sc;
                    float* dst = (mode == 1) ? g_Q : g_K;
                    *(float2*)&dst[(size_t)m * HEADD + nn] = make_float2(ne, no);
                } else {
                    const int nn = (job - 2) * 256 + ncol;
                    *(__half2*)&g_Vh[(size_t)m * VDIM + nn] =
                        __halves2half2(__float2half_rn(e * 64.0f), __float2half_rn(o * 64.0f));
                }
            }
        }
    }
}

// ===========================================================================
// Retention (unchanged from R10): tiered precision, window 10, V fp16.
// ===========================================================================
#define QP 264
#define PS 72
#define PV 136
#define OFF_QH 0
#define OFF_QL (64 * QP)
#define OFF_KH (2 * 64 * QP)
#define OFF_KL (3 * 64 * QP)
#define OFF_SH (4 * 64 * QP)
#define OFF_SL (OFF_SH + 64 * PS)
#define OFF_VB (OFF_SH + 2 * 64 * PS)
#define VPL(buf) (OFF_VB + (buf) * 64 * PV)
#define RET_SMEM ((OFF_VB + 2 * 64 * PV) * 2)

__global__ void __launch_bounds__(256, 1) retention_kernel(float* __restrict__ Out)
{
    extern __shared__ __align__(16) __half sm[];
    const uint32_t sb = smem_u32(sm);

    const int tid = threadIdx.x, wid = tid >> 5, lane = tid & 31;
    const int g = lane >> 2, tg = lane & 3;
    const int vh = blockIdx.x;
    const int qt = (int)gridDim.y - 1 - (int)blockIdx.y;   // heavy CTAs first
    const int b = blockIdx.z;
    const int q0 = qt * 64, base = b * SEQ;

    const int wm  = (wid >> 2) * 32;
    const int wn  = (wid & 3) * 16;
    const int wvc = (wid & 3) * 32;

    const int arow_f = lane & 15;
    const int acol_f = (lane >> 4) << 3;
    const int brow_f = (lane & 7) + ((lane >> 3) & 1) * 8;
    const int krow_f = lane & 7;
    const int kcol_f = ((lane >> 3) & 1) * 8;

    const int kt_lo = (qt >= WINDOW - 1) ? qt - (WINDOW - 1) : 0;

    const int c4 = (tid & 63) * 4;
    const float lg0 = __log2f(((float)c4 + 102.4f) * (1.0f / 358.4f));
    const float lg1 = __log2f(((float)c4 + 104.4f) * (1.0f / 358.4f));
    const float eq = (float)q0 * (1.0f / 512.0f);
    const float fq0 = exp2f(-lg0 * eq + 6.0f), fq1 = exp2f(-lg1 * eq + 6.0f);
    const float fk0 = exp2f( lg0 * eq + 6.0f), fk1 = exp2f( lg1 * eq + 6.0f);

    auto issue_v = [&](int buf, int k0, int c) {
        const int colbase = vh * 256 + c * 128;
#pragma unroll
        for (int i = 0; i < 4; i++) {
            const int j = tid + i * 256;
            const int row = j >> 4, col8 = (j & 15) * 8;
            cp_async16(sb + (uint32_t)(VPL(buf) + row * PV + col8) * 2,
                       g_Vh + (size_t)(base + k0 + row) * VDIM + colbase + col8);
        }
        CP_COMMIT();
    };

    issue_v(0, kt_lo * 64, 0);

#pragma unroll 4
    for (int i = 0; i < 16; i++) {
        const int row = (tid + i * 256) >> 6;
        float4 v = *(const float4*)(g_Q + (size_t)(base + q0 + row) * HEADD + c4);
        __half h0, l0h, h1, l1h, h2, l2h, h3, l3h;
        hsplit(v.x * fq0, h0, l0h); hsplit(v.y * fq0, h1, l1h);
        hsplit(v.z * fq1, h2, l2h); hsplit(v.w * fq1, h3, l3h);
        __half* ph = sm + OFF_QH + row * QP + c4;
        __half* pl = sm + OFF_QL + row * QP + c4;
        *(__half2*)(ph) = __halves2half2(h0, h1);  *(__half2*)(ph + 2) = __halves2half2(h2, h3);
        *(__half2*)(pl) = __halves2half2(l0h, l1h); *(__half2*)(pl + 2) = __halves2half2(l2h, l3h);
    }

    float o[2][8][4];
#pragma unroll
    for (int a = 0; a < 2; a++)
#pragma unroll
        for (int n = 0; n < 8; n++)
#pragma unroll
            for (int c = 0; c < 4; c++) o[a][n][c] = 0.0f;

    int vbuf = 0;

    for (int kt = kt_lo; kt <= qt; kt++) {
        const int k0 = kt * 64;
        const bool full3 = (kt >= qt - 1);

#pragma unroll 4
        for (int i = 0; i < 16; i++) {
            const int row = (tid + i * 256) >> 6;
            float4 v = *(const float4*)(g_K + (size_t)(base + k0 + row) * HEADD + c4);
            __half h0, l0h, h1, l1h, h2, l2h, h3, l3h;
            hsplit(v.x * fk0, h0, l0h); hsplit(v.y * fk0, h1, l1h);
            hsplit(v.z * fk1, h2, l2h); hsplit(v.w * fk1, h3, l3h);
            __half* ph = sm + OFF_KH + row * QP + c4;
            *(__half2*)(ph) = __halves2half2(h0, h1);  *(__half2*)(ph + 2) = __halves2half2(h2, h3);
            if (full3) {
                __half* pl = sm + OFF_KL + row * QP + c4;
                *(__half2*)(pl) = __halves2half2(l0h, l1h); *(__half2*)(pl + 2) = __halves2half2(l2h, l3h);
            }
        }
        __syncthreads();

        float s4[2][2][4];
#pragma unroll
        for (int a = 0; a < 2; a++)
#pragma unroll
            for (int n = 0; n < 2; n++)
#pragma unroll
                for (int c = 0; c < 4; c++) s4[a][n][c] = 0.0f;

        if (full3) {
#pragma unroll 4
            for (int ks = 0; ks < 16; ks++) {
                const int kk = ks * 16;
                uint32_t ah[2][4], al[2][4], bh[2][2], bl[2][2];
#pragma unroll
                for (int mf = 0; mf < 2; mf++) {
                    const uint32_t off = (uint32_t)((wm + mf * 16 + arow_f) * QP + kk + acol_f) * 2;
                    ldm_x4(ah[mf], sb + (uint32_t)OFF_QH * 2 + off);
                    ldm_x4(al[mf], sb + (uint32_t)OFF_QL * 2 + off);
                }
#pragma unroll
                for (int nf = 0; nf < 2; nf++) {
                    const uint32_t off = (uint32_t)((wn + nf * 8 + krow_f) * QP + kk + kcol_f) * 2;
                    ldm_x2(bh[nf], sb + (uint32_t)OFF_KH * 2 + off);
                    ldm_x2(bl[nf], sb + (uint32_t)OFF_KL * 2 + off);
                }
#pragma unroll
                for (int mf = 0; mf < 2; mf++)
#pragma unroll
                    for (int nf = 0; nf < 2; nf++)
                        mma3(s4[mf][nf], ah[mf], al[mf], bh[nf], bl[nf]);
            }
        } else {
#pragma unroll 4
            for (int ks = 0; ks < 16; ks++) {
                const int kk = ks * 16;
                uint32_t ah[2][4], bh[2][2];
#pragma unroll
                for (int mf = 0; mf < 2; mf++) {
                    const uint32_t off = (uint32_t)((wm + mf * 16 + arow_f) * QP + kk + acol_f) * 2;
                    ldm_x4(ah[mf], sb + (uint32_t)OFF_QH * 2 + off);
                }
#pragma unroll
                for (int nf = 0; nf < 2; nf++) {
                    const uint32_t off = (uint32_t)((wn + nf * 8 + krow_f) * QP + kk + kcol_f) * 2;
                    ldm_x2(bh[nf], sb + (uint32_t)OFF_KH * 2 + off);
                }
#pragma unroll
                for (int mf = 0; mf < 2; mf++)
#pragma unroll
                    for (int nf = 0; nf < 2; nf++)
                        mma16(s4[mf][nf], ah[mf], bh[nf]);
            }
        }

        if (kt < qt) {
#pragma unroll
            for (int mf = 0; mf < 2; mf++) {
                const int q_l = wm + mf * 16 + g;
                const int dq0 = (q0 - k0) + q_l - (wn + 2 * tg);
                const float d00 = exp2f((float)dq0 * LOG2_GAMMA);
#pragma unroll
                for (int nf = 0; nf < 2; nf++) {
                    const int k_l = wn + nf * 8 + 2 * tg;
                    const float dc0 = (nf == 0) ? d00 : d00 * GAMMA_M8;
                    const float dc1 = dc0 * GAMMA_INV;
                    const float dc2 = dc0 * GAMMA_P8;
                    const float dc3 = dc2 * GAMMA_INV;
                    if (full3) {
                        __half h0, l0h, h1, l1h;
                        hsplit(s4[mf][nf][0] * dc0, h0, l0h);
                        hsplit(s4[mf][nf][1] * dc1, h1, l1h);
                        *(__half2*)(sm + OFF_SH + q_l * PS + k_l) = __halves2half2(h0, h1);
                        *(__half2*)(sm + OFF_SL + q_l * PS + k_l) = __halves2half2(l0h, l1h);
                        hsplit(s4[mf][nf][2] * dc2, h0, l0h);
                        hsplit(s4[mf][nf][3] * dc3, h1, l1h);
                        *(__half2*)(sm + OFF_SH + (q_l + 8) * PS + k_l) = __halves2half2(h0, h1);
                        *(__half2*)(sm + OFF_SL + (q_l + 8) * PS + k_l) = __halves2half2(l0h, l1h);
                    } else {
                        *(__half2*)(sm + OFF_SH + q_l * PS + k_l) =
                            __halves2half2(__float2half_rn(s4[mf][nf][0] * dc0),
                                           __float2half_rn(s4[mf][nf][1] * dc1));
                        *(__half2*)(sm + OFF_SH + (q_l + 8) * PS + k_l) =
                            __halves2half2(__float2half_rn(s4[mf][nf][2] * dc2),
                                           __float2half_rn(s4[mf][nf][3] * dc3));
                    }
                }
            }
        } else {
#pragma unroll
            for (int mf = 0; mf < 2; mf++) {
                const int q_l = wm + mf * 16 + g;
#pragma unroll
                for (int nf = 0; nf < 2; nf++) {
                    const int k_l = wn + nf * 8 + 2 * tg;
#pragma unroll
                    for (int c = 0; c < 4; c += 2) {
                        const int qq = q_l + (c >> 1) * 8;
                        __half h0, l0h, h1, l1h;
                        const int d0 = qq - k_l;
                        const float dec0 = (d0 >= 0) ? exp2f((float)d0 * LOG2_GAMMA) : 0.0f;
                        const float dec1 = (d0 - 1 >= 0) ? dec0 * GAMMA_INV : 0.0f;
                        hsplit(s4[mf][nf][c] * dec0, h0, l0h);
                        hsplit(s4[mf][nf][c + 1] * dec1, h1, l1h);
                        *(__half2*)(sm + OFF_SH + qq * PS + k_l) = __halves2half2(h0, h1);
                        *(__half2*)(sm + OFF_SL + qq * PS + k_l) = __halves2half2(l0h, l1h);
                    }
                }
            }
        }
        __syncthreads();

        for (int c = 0; c < 2; c++) {
            const bool last = (kt == qt) && (c == 1);
            if (!last) {
                if (c == 0) issue_v(vbuf ^ 1, k0, 1);
                else        issue_v(vbuf ^ 1, k0 + 64, 0);
                CP_WAIT(1);
            } else {
                CP_WAIT(0);
            }
            __syncthreads();

            if (full3) {
#pragma unroll
                for (int ks = 0; ks < 4; ks++) {
                    const int kk = ks * 16;
                    uint32_t ah[2][4], al[2][4], bh[4][2];
#pragma unroll
                    for (int mf = 0; mf < 2; mf++) {
                        const uint32_t off = (uint32_t)((wm + mf * 16 + arow_f) * PS + kk + acol_f) * 2;
                        ldm_x4(ah[mf], sb + (uint32_t)OFF_SH * 2 + off);
                        ldm_x4(al[mf], sb + (uint32_t)OFF_SL * 2 + off);
                    }
#pragma unroll
                    for (int nf = 0; nf < 4; nf++) {
                        const uint32_t off = (uint32_t)((kk + brow_f) * PV + wvc + nf * 8) * 2;
                        ldm_x2t(bh[nf], sb + (uint32_t)VPL(vbuf) * 2 + off);
                    }
#pragma unroll
                    for (int mf = 0; mf < 2; mf++)
#pragma unroll
                        for (int nf = 0; nf < 4; nf++) {
                            mma16(o[mf][c * 4 + nf], ah[mf], bh[nf]);
                            mma16(o[mf][c * 4 + nf], al[mf], bh[nf]);
                        }
                }
            } else {
#pragma unroll
                for (int ks = 0; ks < 4; ks++) {
                    const int kk = ks * 16;
                    uint32_t ah[2][4], bh[4][2];
#pragma unroll
                    for (int mf = 0; mf < 2; mf++) {
                        const uint32_t off = (uint32_t)((wm + mf * 16 + arow_f) * PS + kk + acol_f) * 2;
                        ldm_x4(ah[mf], sb + (uint32_t)OFF_SH * 2 + off);
                    }
#pragma unroll
                    for (int nf = 0; nf < 4; nf++) {
                        const uint32_t off = (uint32_t)((kk + brow_f) * PV + wvc + nf * 8) * 2;
                        ldm_x2t(bh[nf], sb + (uint32_t)VPL(vbuf) * 2 + off);
                    }
#pragma unroll
                    for (int mf = 0; mf < 2; mf++)
#pragma unroll
                        for (int nf = 0; nf < 4; nf++)
                            mma16(o[mf][c * 4 + nf], ah[mf], bh[nf]);
                }
            }
            __syncthreads();
            vbuf ^= 1;
        }
    }

    const float inv = 1.0f / 262144.0f;
#pragma unroll
    for (int mf = 0; mf < 2; mf++) {
        const int q_l = wm + mf * 16 + g;
#pragma unroll
        for (int c = 0; c < 2; c++)
#pragma unroll
            for (int nf = 0; nf < 4; nf++) {
                const int v = vh * 256 + c * 128 + wvc + nf * 8 + 2 * tg;
                const size_t r0 = (size_t)(base + q0 + q_l) * VDIM + v;
                float* oo = o[mf][c * 4 + nf];
                *(float2*)&Out[r0]            = make_float2(oo[0] * inv, oo[1] * inv);
                *(float2*)&Out[r0 + 8 * VDIM] = make_float2(oo[2] * inv, oo[3] * inv);
            }
    }
}

// ===========================================================================
extern "C" void kernel_launch(void* const* d_in, const int* in_sizes, int n_in,
                              void* d_out, int out_size)
{
    const float* X  = (const float*)d_in[0];
    const float* WQ = (const float*)d_in[1];
    const float* WK = (const float*)d_in[2];
    const float* WV = (const float*)d_in[3];
    float* out = (float*)d_out;

    cudaFuncSetAttribute(proj_kernel, cudaFuncAttributeMaxDynamicSharedMemorySize, PROJ_SMEM);
    cudaFuncSetAttribute(retention_kernel, cudaFuncAttributeMaxDynamicSharedMemorySize, RET_SMEM);

    pack_x_kernel<<<(size_t)MROWS * HID / (256 * 8), 256>>>(X);
    pack_w_kernel<<<HID * 1024 / (256 * 8), 256>>>(WQ, WK, WV);
    proj_kernel<<<dim3(4, MROWS / 128), 256, PROJ_SMEM>>>();
    retention_kernel<<<dim3(2, SEQ / 64, BATCH), 256, RET_SMEM>>>(out);
}